// round 17
// baseline (speedup 1.0000x reference)
#include <cuda_runtime.h>
#include <math.h>

#define EPSV 1e-5f
#define VFLOOR 1e-6f

// Fixed shape: B=4, L=4096, D=2048, G=16 (gs=128).
constexpr int Lc  = 4096;
constexpr int Gc  = 16;
constexpr int Dc  = 2048;
constexpr int CH  = 8;
constexpr int NCH = Lc / CH;      // 512
constexpr int MAXB = 8;

__device__ float  g_gmT [MAXB * Gc * Lc];   // (b,g,l) group means
__device__ float2 g_stat[MAXB * Gc * Lc];   // (b,g,l) {mean, rstd}

// ---------------------------------------------------------------------------
// K1: group means. Block = 8-row chunk; warp g reduces group g for all 8 rows
// with ONE packed butterfly (rows mapped to lane bits): 9 shuffles total
// instead of 8 x 5-stage trees. After xor1,2,4 lane holds row (lane&7)'s
// octet partial; xor8,16 complete it. Lanes 0..7 store rows 0..7.
// __ldcg: allocate in L2 (for K3's reversed re-read) but skip L1.
// ---------------------------------------------------------------------------
__global__ void __launch_bounds__(512)
k_gm(const float* __restrict__ x)
{
    const unsigned FULL = 0xffffffffu;
    const int b    = blockIdx.x >> 9;
    const int ch   = blockIdx.x & (NCH - 1);
    const int lane = threadIdx.x & 31;
    const int g    = threadIdx.x >> 5;
    const int rowBase = b * Lc + ch * CH;

    const float4* xr = (const float4*)x;
    float s[CH];
    #pragma unroll
    for (int r = 0; r < CH; r++) {
        const float4 t = __ldcg(&xr[(size_t)(rowBase + r) * (Dc / 4) + g * 32 + lane]);
        s[r] = (t.x + t.y) + (t.z + t.w);
    }

    // 8 -> 4 (xor 1): lane bit0 selects row parity
    float a4[4];
    #pragma unroll
    for (int i = 0; i < 4; i++) {
        const float keep = (lane & 1) ? s[2*i+1] : s[2*i];
        const float send = (lane & 1) ? s[2*i]   : s[2*i+1];
        a4[i] = keep + __shfl_xor_sync(FULL, send, 1);
    }
    // 4 -> 2 (xor 2)
    float a2[2];
    #pragma unroll
    for (int i = 0; i < 2; i++) {
        const float keep = (lane & 2) ? a4[2*i+1] : a4[2*i];
        const float send = (lane & 2) ? a4[2*i]   : a4[2*i+1];
        a2[i] = keep + __shfl_xor_sync(FULL, send, 2);
    }
    // 2 -> 1 (xor 4)
    float acc;
    {
        const float keep = (lane & 4) ? a2[1] : a2[0];
        const float send = (lane & 4) ? a2[0] : a2[1];
        acc = keep + __shfl_xor_sync(FULL, send, 4);
    }
    // finish across octets
    acc += __shfl_xor_sync(FULL, acc, 8);
    acc += __shfl_xor_sync(FULL, acc, 16);

    if (lane < CH)
        g_gmT[(b * Gc + g) * Lc + ch * CH + lane] = acc * (1.0f / 128.0f);
}

// ---------------------------------------------------------------------------
// K2: per-(b,g) scan over L using the Chan closed form (validated R7/R12):
// one hierarchical scan of (S, Q, C), then mean/var directly per element.
// 64 blocks, 512 threads, 8 elems/thread. Vectorized gm/mask loads
// (2x float4 + 2x int4 per thread). Emits (mean,rstd) float2 + tail.
// ---------------------------------------------------------------------------
__global__ void __launch_bounds__(512)
k_scan(const int* __restrict__ prev_count,
       const float* __restrict__ prev_mean,
       const float* __restrict__ prev_var,
       const int* __restrict__ pmask,
       float* __restrict__ outF,
       int B, int writeTail, long long tailOff)
{
    constexpr int P = 8;
    const int b = blockIdx.x / Gc;
    const int g = blockIdx.x - b * Gc;
    const int tid  = threadIdx.x;
    const int lane = tid & 31;
    const int wid  = tid >> 5;
    const unsigned FULL = 0xffffffffu;

    const float pc     = (float)prev_count[b];
    const float pmeanv = prev_mean[b * Gc + g];
    const float pvarv  = prev_var[b * Gc + g];
    const float psum   = pmeanv * pc;
    const float pm2    = pvarv * fmaxf(pc, 1.0f);

    __shared__ float smS[16], smQ[16], smC[16];

    // vector loads: 8 consecutive gm floats + 8 consecutive mask ints
    const float4* gm4 = (const float4*)&g_gmT[(b * Gc + g) * Lc];
    const int4*   pm4 = (const int4*)(pmask + b * Lc);
    const float4 ga = gm4[tid * 2], gb = gm4[tid * 2 + 1];
    const int4   ma = pm4[tid * 2], mb = pm4[tid * 2 + 1];
    float gv[P] = { ga.x, ga.y, ga.z, ga.w, gb.x, gb.y, gb.z, gb.w };
    float vv[P] = { ma.x ? 1.f : 0.f, ma.y ? 1.f : 0.f, ma.z ? 1.f : 0.f, ma.w ? 1.f : 0.f,
                    mb.x ? 1.f : 0.f, mb.y ? 1.f : 0.f, mb.z ? 1.f : 0.f, mb.w ? 1.f : 0.f };

    // thread-local inclusive scan of (gm*v, gm^2*v, v)
    float ls[P], lq[P], lc[P];
    float sa = 0.f, qa = 0.f, ca = 0.f;
    #pragma unroll
    for (int j = 0; j < P; j++) {
        sa += gv[j] * vv[j];
        qa += gv[j] * gv[j] * vv[j];
        ca += vv[j];
        ls[j] = sa; lq[j] = qa; lc[j] = ca;
    }

    // warp inclusive scan of thread totals
    float ws = sa, wq = qa, wc = ca;
    #pragma unroll
    for (int o = 1; o < 32; o <<= 1) {
        const float ns = __shfl_up_sync(FULL, ws, o);
        const float nq = __shfl_up_sync(FULL, wq, o);
        const float nc = __shfl_up_sync(FULL, wc, o);
        if (lane >= o) { ws += ns; wq += nq; wc += nc; }
    }
    const float exs = ws - sa, exq = wq - qa, exc = wc - ca;

    if (lane == 31) { smS[wid] = ws; smQ[wid] = wq; smC[wid] = wc; }
    __syncthreads();
    if (tid == 0) {
        float rs = 0.f, rq = 0.f, rc = 0.f;
        #pragma unroll
        for (int i = 0; i < 16; i++) {
            const float ts = smS[i], tq = smQ[i], tc = smC[i];
            smS[i] = rs; smQ[i] = rq; smC[i] = rc;
            rs += ts; rq += tq; rc += tc;
        }
    }
    __syncthreads();
    const float baseS = smS[wid] + exs;
    const float baseQ = smQ[wid] + exq;
    const float baseC = smC[wid] + exc;

    float2* statrow = &g_stat[(size_t)(b * Gc + g) * Lc];
    #pragma unroll
    for (int j = 0; j < P; j++) {
        const int l = tid * P + j;
        const float S = baseS + ls[j];
        const float Q = baseQ + lq[j];
        const float C = baseC + lc[j];
        const float count_t = pc + C;

        float mean_t = pmeanv, var = pvarv;
        if (count_t > 0.0f) {
            mean_t = (psum + S) / fmaxf(count_t, 1.0f);
            float sumdd = 0.0f;
            if (C > 0.0f) {
                const float bm  = S / C;
                const float m2b = Q - bm * S;
                const float dlt = bm - pmeanv;
                sumdd = m2b + dlt * dlt * (pc * C / (pc + C));
            }
            var = (pm2 + sumdd) / fmaxf(count_t, 1.0f);
        }
        var = fmaxf(var, VFLOOR);
        statrow[l] = make_float2(mean_t, rsqrtf(var + EPSV));
        if (writeTail && l == Lc - 1) {
            outF[tailOff + B + b * Gc + g]                  = mean_t;
            outF[tailOff + B + (size_t)B * Gc + b * Gc + g] = var;
            if (g == 0) outF[tailOff + b] = count_t;
        }
    }
}

// ---------------------------------------------------------------------------
// K3: pure elementwise normalize (champion shape), REVERSED block order
// (first wave reads the tail of x, still L2-resident from K1). NV=8 per
// thread as two pipelined groups of 4. x read evict-first (__ldcs);
// y written evict-first (__stcs).
// ---------------------------------------------------------------------------
__global__ void __launch_bounds__(512)
k_norm(const float* __restrict__ x,
       const float* __restrict__ wgt,
       const float* __restrict__ bias,
       float* __restrict__ outF)
{
    constexpr int NV = 8;                        // 2 groups of 4
    const int tid = threadIdx.x;
    const int rbid = gridDim.x - 1 - blockIdx.x;          // reversed order
    const long long base = (long long)rbid * (512 * NV) + tid;

    const int d4 = (int)(base & 511);            // invariant across k (stride 512)
    float4 wv = ((const float4*)wgt)[d4];
    float4 bv = ((const float4*)bias)[d4];
    wv.x += 1.f; wv.y += 1.f; wv.z += 1.f; wv.w += 1.f;

    const float4* xr = (const float4*)x;
    float4* yr = (float4*)outF;

    #pragma unroll
    for (int h = 0; h < 2; h++) {
        const long long idx0 = base + (long long)h * 4 * 512;
        float4 v[4];
        float2 st[4];
        #pragma unroll
        for (int k = 0; k < 4; k++) {
            const long long idx = idx0 + (long long)k * 512;
            v[k] = __ldcs(&xr[idx]);
            const int row = (int)(idx >> 9);     // b*Lc + l
            const int g   = ((int)idx >> 5) & 15;
            const int b   = row >> 12;
            const int l   = row & (Lc - 1);
            st[k] = g_stat[((size_t)(b * Gc + g)) * Lc + l];
        }
        #pragma unroll
        for (int k = 0; k < 4; k++) {
            const long long idx = idx0 + (long long)k * 512;
            const float mn = st[k].x, rs = st[k].y;
            float4 o;
            o.x = (v[k].x - mn) * rs * wv.x + bv.x;
            o.y = (v[k].y - mn) * rs * wv.y + bv.y;
            o.z = (v[k].z - mn) * rs * wv.z + bv.z;
            o.w = (v[k].w - mn) * rs * wv.w + bv.w;
            __stcs(&yr[idx], o);
        }
    }
}

// ---------------------------------------------------------------------------
extern "C" void kernel_launch(void* const* d_in, const int* in_sizes, int n_in,
                              void* d_out, int out_size)
{
    const float* x     = (const float*)d_in[0];
    const int*   pcnt  = (const int*)d_in[1];
    const float* pmean = (const float*)d_in[2];
    const float* pvar  = (const float*)d_in[3];
    const int*   pmask = (const int*)d_in[4];
    const float* wgt   = (const float*)d_in[5];
    const float* bias  = (const float*)d_in[6];
    float*       outF  = (float*)d_out;

    const int B = in_sizes[1];
    const int G = in_sizes[2] / B;     // 16
    const int D = in_sizes[5];         // 2048
    const int L = in_sizes[4] / B;     // 4096
    (void)G; (void)D; (void)L;

    const long long BLD = (long long)B * L * D;
    const long long expected = BLD + B + 2LL * B * G;
    const int writeTail = (out_size >= expected) ? 1 : 0;

    k_gm  <<<B * NCH, 512>>>(x);
    k_scan<<<B * Gc, 512>>>(pcnt, pmean, pvar, pmask, outF, B, writeTail, BLD);

    const long long n4 = BLD / 4;                 // 8M float4
    const int blocks = (int)(n4 / (512 * 8));     // 2048
    k_norm<<<blocks, 512>>>(x, wgt, bias, outF);
}